// round 1
// baseline (speedup 1.0000x reference)
#include <cuda_runtime.h>
#include <math.h>

// Problem shape (fixed by the reference)
#define BQ 64
#define SQ 197
#define DQ 768
#define HQ 3072
#define MQ (BQ * SQ)  // 12608

// Scratch in device globals (no allocation allowed in kernel_launch)
__device__ float g_h[(size_t)MQ * HQ];      // GEMM1 output (post-GELU), ~155 MB
__device__ float g_wq1[(size_t)HQ * DQ];    // ternarized w1 in {-1,0,1}
__device__ float g_wq2[(size_t)DQ * HQ];    // ternarized w2 in {-1,0,1}
__device__ float g_partial[1024];           // reduction partials (512 per weight)
__device__ float g_gamma[2];                // absmean scales

// ---------------------------------------------------------------------------
// Stage 1: per-block |w| partial sums (deterministic: fixed grid partitioning)
// ---------------------------------------------------------------------------
__global__ void abs_sum_kernel(const float* __restrict__ w, int n, int slot) {
    __shared__ float sdata[256];
    float s = 0.0f;
    for (int i = blockIdx.x * blockDim.x + threadIdx.x; i < n;
         i += gridDim.x * blockDim.x)
        s += fabsf(w[i]);
    sdata[threadIdx.x] = s;
    __syncthreads();
    #pragma unroll
    for (int off = 128; off > 0; off >>= 1) {
        if (threadIdx.x < off) sdata[threadIdx.x] += sdata[threadIdx.x + off];
        __syncthreads();
    }
    if (threadIdx.x == 0) g_partial[slot * 512 + blockIdx.x] = sdata[0];
}

// ---------------------------------------------------------------------------
// Stage 2: fold 512 partials per weight -> gamma = mean(|w|) + 1e-5
// ---------------------------------------------------------------------------
__global__ void finalize_gamma_kernel(int n1, int n2) {
    __shared__ float sdata[512];
    int t = threadIdx.x;

    sdata[t] = g_partial[t];
    __syncthreads();
    #pragma unroll
    for (int off = 256; off > 0; off >>= 1) {
        if (t < off) sdata[t] += sdata[t + off];
        __syncthreads();
    }
    if (t == 0) g_gamma[0] = sdata[0] / (float)n1 + 1e-5f;
    __syncthreads();

    sdata[t] = g_partial[512 + t];
    __syncthreads();
    #pragma unroll
    for (int off = 256; off > 0; off >>= 1) {
        if (t < off) sdata[t] += sdata[t + off];
        __syncthreads();
    }
    if (t == 0) g_gamma[1] = sdata[0] / (float)n2 + 1e-5f;
}

// ---------------------------------------------------------------------------
// Ternarize: wq = clip(round(w/gamma), -1, 1)   (gamma folded in at GEMM time)
// rintf = round-half-to-even, matching jnp.round.
// ---------------------------------------------------------------------------
__global__ void quant_kernel(const float* __restrict__ w, float* __restrict__ wq,
                             int n, int slot) {
    int i = blockIdx.x * blockDim.x + threadIdx.x;
    if (i >= n) return;
    float inv = 1.0f / g_gamma[slot];
    float q = rintf(w[i] * inv);
    q = fminf(1.0f, fmaxf(-1.0f, q));
    wq[i] = q;
}

// ---------------------------------------------------------------------------
// Tiled SGEMM: C[M,N] = act( gamma * (A[M,K] @ Bw[N,K]^T) + bias[N] )
//   BM=BN=128, BK=8, 256 threads, 8x8 per-thread microtile.
//   GELU_FLAG: exact gelu (erf form) fused in epilogue.
// ---------------------------------------------------------------------------
template <int GELU_FLAG>
__global__ __launch_bounds__(256)
void gemm_bias_act_kernel(const float* __restrict__ A,
                          const float* __restrict__ Bw,
                          const float* __restrict__ bias,
                          float* __restrict__ C,
                          int M, int N, int K, int gslot) {
    constexpr int BM = 128, BN = 128, BK = 8, TM = 8, TN = 8;
    __shared__ float As[BK][BM];
    __shared__ float Bs[BK][BN];

    const int tid  = threadIdx.x;        // 0..255
    const int tcol = tid & 15;           // 16 thread-cols along N
    const int trow = tid >> 4;           // 16 thread-rows along M
    const int m0 = blockIdx.y * BM;
    const int n0 = blockIdx.x * BN;

    // load mapping: 256 threads x 1 float4 covers a 128x8 tile
    const int l_row = tid >> 1;          // 0..127
    const int l_col = (tid & 1) * 4;     // 0 or 4

    const float gamma = g_gamma[gslot];

    float acc[TM][TN];
    #pragma unroll
    for (int i = 0; i < TM; i++)
        #pragma unroll
        for (int j = 0; j < TN; j++) acc[i][j] = 0.0f;

    for (int k0 = 0; k0 < K; k0 += BK) {
        // A tile (guard M edge)
        float4 av = make_float4(0.f, 0.f, 0.f, 0.f);
        int gm = m0 + l_row;
        if (gm < M)
            av = *(const float4*)(A + (size_t)gm * K + k0 + l_col);
        As[l_col + 0][l_row] = av.x;
        As[l_col + 1][l_row] = av.y;
        As[l_col + 2][l_row] = av.z;
        As[l_col + 3][l_row] = av.w;

        // B tile: Bw is [N,K] row-major; N here is always a multiple of 128
        int gn = n0 + l_row;
        float4 bv = *(const float4*)(Bw + (size_t)gn * K + k0 + l_col);
        Bs[l_col + 0][l_row] = bv.x;
        Bs[l_col + 1][l_row] = bv.y;
        Bs[l_col + 2][l_row] = bv.z;
        Bs[l_col + 3][l_row] = bv.w;

        __syncthreads();

        #pragma unroll
        for (int kk = 0; kk < BK; kk++) {
            float a[TM], b[TN];
            #pragma unroll
            for (int i = 0; i < TM; i++) a[i] = As[kk][trow * TM + i];
            #pragma unroll
            for (int j = 0; j < TN; j++) b[j] = Bs[kk][tcol * TN + j];
            #pragma unroll
            for (int i = 0; i < TM; i++)
                #pragma unroll
                for (int j = 0; j < TN; j++) acc[i][j] += a[i] * b[j];
        }
        __syncthreads();
    }

    // epilogue: scale by gamma, add bias, optional exact GELU
    #pragma unroll
    for (int i = 0; i < TM; i++) {
        int gm = m0 + trow * TM + i;
        if (gm >= M) continue;
        #pragma unroll
        for (int j = 0; j < TN; j++) {
            int gn = n0 + tcol * TN + j;
            float v = acc[i][j] * gamma + bias[gn];
            if (GELU_FLAG)
                v = 0.5f * v * (1.0f + erff(v * 0.70710678118654752f));
            C[(size_t)gm * N + gn] = v;
        }
    }
}

// ---------------------------------------------------------------------------
// Launch: gammas -> quantize -> GEMM1(+GELU) -> GEMM2
// ---------------------------------------------------------------------------
extern "C" void kernel_launch(void* const* d_in, const int* in_sizes, int n_in,
                              void* d_out, int out_size) {
    const float* x  = (const float*)d_in[0];
    const float* w1 = (const float*)d_in[1];
    const float* b1 = (const float*)d_in[2];
    const float* w2 = (const float*)d_in[3];
    const float* b2 = (const float*)d_in[4];
    float* out = (float*)d_out;

    float *p_h, *p_wq1, *p_wq2;
    cudaGetSymbolAddress((void**)&p_h,   g_h);
    cudaGetSymbolAddress((void**)&p_wq1, g_wq1);
    cudaGetSymbolAddress((void**)&p_wq2, g_wq2);

    const int NW1 = HQ * DQ;  // 2359296
    const int NW2 = DQ * HQ;  // 2359296

    abs_sum_kernel<<<512, 256>>>(w1, NW1, 0);
    abs_sum_kernel<<<512, 256>>>(w2, NW2, 1);
    finalize_gamma_kernel<<<1, 512>>>(NW1, NW2);

    quant_kernel<<<(NW1 + 255) / 256, 256>>>(w1, p_wq1, NW1, 0);
    quant_kernel<<<(NW2 + 255) / 256, 256>>>(w2, p_wq2, NW2, 1);

    // GEMM1: [M, D] x [H, D]^T -> [M, H], + b1, exact GELU
    {
        dim3 grid(HQ / 128, (MQ + 127) / 128);
        gemm_bias_act_kernel<1><<<grid, 256>>>(x, p_wq1, b1, p_h, MQ, HQ, DQ, 0);
    }
    // GEMM2: [M, H] x [D, H]^T -> [M, D], + b2
    {
        dim3 grid(DQ / 128, (MQ + 127) / 128);
        gemm_bias_act_kernel<0><<<grid, 256>>>(p_h, p_wq2, b2, out, MQ, DQ, HQ, 1);
    }
}

// round 3
// speedup vs baseline: 3.1549x; 3.1549x over previous
#include <cuda_runtime.h>
#include <cuda_bf16.h>
#include <math.h>
#include <stdint.h>

// Problem shape (fixed by the reference)
#define BQ 64
#define SQ 197
#define DQ 768
#define HQ 3072
#define MQ (BQ * SQ)  // 12608

// ---------------------------------------------------------------------------
// Device global scratch (no allocation allowed)
// ---------------------------------------------------------------------------
__device__ __nv_bfloat162 g_xs [(size_t)MQ * DQ];   // x split: (hi,lo) per k
__device__ __nv_bfloat162 g_hs [(size_t)MQ * HQ];   // h split: (hi,lo) per k
__device__ __nv_bfloat162 g_w1d[(size_t)HQ * DQ];   // ternary w1 duplicated
__device__ __nv_bfloat162 g_w2d[(size_t)DQ * HQ];   // ternary w2 duplicated
__device__ float g_partial[1024];
__device__ float g_gamma[2];

__device__ __forceinline__ uint32_t smem_u32(const void* p) {
    uint32_t a;
    asm("{ .reg .u64 t; cvta.to.shared.u64 t, %1; cvt.u32.u64 %0, t; }"
        : "=r"(a) : "l"(p));
    return a;
}

// ---------------------------------------------------------------------------
// Prep kernels (unchanged from R1 — proven correct)
// ---------------------------------------------------------------------------
__global__ void abs_sum_kernel(const float* __restrict__ w, int n, int slot) {
    __shared__ float sdata[256];
    float s = 0.0f;
    for (int i = blockIdx.x * blockDim.x + threadIdx.x; i < n;
         i += gridDim.x * blockDim.x)
        s += fabsf(w[i]);
    sdata[threadIdx.x] = s;
    __syncthreads();
    #pragma unroll
    for (int off = 128; off > 0; off >>= 1) {
        if (threadIdx.x < off) sdata[threadIdx.x] += sdata[threadIdx.x + off];
        __syncthreads();
    }
    if (threadIdx.x == 0) g_partial[slot * 512 + blockIdx.x] = sdata[0];
}

__global__ void finalize_gamma_kernel(int n1, int n2) {
    __shared__ float sdata[512];
    int t = threadIdx.x;
    sdata[t] = g_partial[t];
    __syncthreads();
    #pragma unroll
    for (int off = 256; off > 0; off >>= 1) {
        if (t < off) sdata[t] += sdata[t + off];
        __syncthreads();
    }
    if (t == 0) g_gamma[0] = sdata[0] / (float)n1 + 1e-5f;
    __syncthreads();
    sdata[t] = g_partial[512 + t];
    __syncthreads();
    #pragma unroll
    for (int off = 256; off > 0; off >>= 1) {
        if (t < off) sdata[t] += sdata[t + off];
        __syncthreads();
    }
    if (t == 0) g_gamma[1] = sdata[0] / (float)n2 + 1e-5f;
}

__global__ void quant_dup_kernel(const float* __restrict__ w,
                                 __nv_bfloat162* __restrict__ wd, int n, int slot) {
    int i = blockIdx.x * blockDim.x + threadIdx.x;
    if (i >= n) return;
    float inv = 1.0f / g_gamma[slot];
    float q = rintf(w[i] * inv);
    q = fminf(1.0f, fmaxf(-1.0f, q));
    __nv_bfloat16 qb = __float2bfloat16(q);   // exact: q in {-1,0,1}
    __nv_bfloat162 p; p.x = qb; p.y = qb;
    wd[i] = p;
}

__global__ void split_kernel(const float* __restrict__ x,
                             __nv_bfloat162* __restrict__ xs, int n) {
    int i = blockIdx.x * blockDim.x + threadIdx.x;
    if (i >= n) return;
    float v = x[i];
    __nv_bfloat16 hi = __float2bfloat16(v);
    __nv_bfloat16 lo = __float2bfloat16(v - __bfloat162float(hi));
    __nv_bfloat162 p; p.x = hi; p.y = lo;
    xs[i] = p;
}

// ---------------------------------------------------------------------------
// HMMA GEMM: C[M,N] = epi( gamma * (A[M,Kp] @ B[N,Kp]^T) + bias[N] )
//   A,B bf16 row-major (K contiguous). 128x128 CTA tile, 8 warps, each warp
//   64x32 via mma.sync.m16n8k16. SMEM: swizzled 128x64 tiles, double-buffered
//   cp.async.
// ---------------------------------------------------------------------------
template <int GELU_SPLIT>
__global__ __launch_bounds__(256, 2)
void hmma_gemm(const __nv_bfloat16* __restrict__ A,
               const __nv_bfloat16* __restrict__ B,
               const float* __restrict__ bias,
               void* __restrict__ Cout,
               int M, int N, int Kp, int gslot) {
    extern __shared__ char smem[];
    const uint32_t sb = smem_u32(smem);
    const int tid  = threadIdx.x;
    const int wid  = tid >> 5;
    const int lane = tid & 31;
    const int m0 = blockIdx.y * 128;
    const int n0 = blockIdx.x * 128;
    const int wm = wid & 1;    // 2 m-blocks of 64
    const int wn = wid >> 1;   // 4 n-blocks of 32

    // load mapping for one 128x64 bf16 tile (16KB): 256 thr x 4 x 16B
    const int nch = Kp >> 6;   // chunks of 64 bf16

    float acc[4][4][4];
    #pragma unroll
    for (int i = 0; i < 4; i++)
        #pragma unroll
        for (int j = 0; j < 4; j++)
            #pragma unroll
            for (int k = 0; k < 4; k++) acc[i][j][k] = 0.0f;

    // ---- chunk loader (cp.async, zfill on M edge) ----
    auto load_chunk = [&](int c) {
        const int buf = c & 1;
        const uint32_t offA = buf * 32768u;
        const uint32_t offB = offA + 16384u;
        const __nv_bfloat16* Ag = A + (size_t)m0 * Kp + (size_t)c * 64;
        const __nv_bfloat16* Bg = B + (size_t)n0 * Kp + (size_t)c * 64;
        #pragma unroll
        for (int t = 0; t < 4; t++) {
            int idx = tid + t * 256;            // 0..1023
            int row = idx >> 3;
            int c16 = idx & 7;
            uint32_t bo = (uint32_t)row * 128u + (uint32_t)c16 * 16u;
            uint32_t sw = bo ^ ((bo >> 3) & 0x70u);
            const void* ga = Ag + (size_t)row * Kp + c16 * 8;
            uint32_t na = (m0 + row < M) ? 16u : 0u;
            asm volatile("cp.async.cg.shared.global [%0], [%1], 16, %2;"
                         :: "r"(sb + offA + sw), "l"(ga), "r"(na));
            const void* gb = Bg + (size_t)row * Kp + c16 * 8;
            asm volatile("cp.async.cg.shared.global [%0], [%1], 16;"
                         :: "r"(sb + offB + sw), "l"(gb));
        }
        asm volatile("cp.async.commit_group;" ::: "memory");
    };

    // ---- compute one chunk from buffer buf ----
    auto compute_chunk = [&](int buf) {
        const uint32_t offA = buf * 32768u;
        const uint32_t offB = offA + 16384u;
        #pragma unroll
        for (int kk = 0; kk < 64; kk += 16) {
            uint32_t a[4][4];
            #pragma unroll
            for (int mi = 0; mi < 4; mi++) {
                int r = wm * 64 + mi * 16 + (lane & 15);
                uint32_t bo = (uint32_t)r * 128u
                            + (uint32_t)(kk + ((lane >> 4) << 3)) * 2u;
                uint32_t sw = bo ^ ((bo >> 3) & 0x70u);
                asm volatile(
                    "ldmatrix.sync.aligned.m8n8.x4.shared.b16 {%0,%1,%2,%3}, [%4];"
                    : "=r"(a[mi][0]), "=r"(a[mi][1]), "=r"(a[mi][2]), "=r"(a[mi][3])
                    : "r"(sb + offA + sw));
            }
            uint32_t b[4][2];
            #pragma unroll
            for (int nj = 0; nj < 2; nj++) {
                int r = wn * 32 + nj * 16 + (lane & 7) + ((lane >> 4) << 3);
                uint32_t bo = (uint32_t)r * 128u
                            + (uint32_t)(kk + (lane & 8)) * 2u;
                uint32_t sw = bo ^ ((bo >> 3) & 0x70u);
                uint32_t b0, b1, b2, b3;
                asm volatile(
                    "ldmatrix.sync.aligned.m8n8.x4.shared.b16 {%0,%1,%2,%3}, [%4];"
                    : "=r"(b0), "=r"(b1), "=r"(b2), "=r"(b3)
                    : "r"(sb + offB + sw));
                b[nj * 2 + 0][0] = b0; b[nj * 2 + 0][1] = b1;
                b[nj * 2 + 1][0] = b2; b[nj * 2 + 1][1] = b3;
            }
            #pragma unroll
            for (int mi = 0; mi < 4; mi++)
                #pragma unroll
                for (int ni = 0; ni < 4; ni++)
                    asm volatile(
                        "mma.sync.aligned.m16n8k16.row.col.f32.bf16.bf16.f32 "
                        "{%0,%1,%2,%3}, {%4,%5,%6,%7}, {%8,%9}, {%0,%1,%2,%3};"
                        : "+f"(acc[mi][ni][0]), "+f"(acc[mi][ni][1]),
                          "+f"(acc[mi][ni][2]), "+f"(acc[mi][ni][3])
                        : "r"(a[mi][0]), "r"(a[mi][1]), "r"(a[mi][2]), "r"(a[mi][3]),
                          "r"(b[ni][0]), "r"(b[ni][1]));
        }
    };

    load_chunk(0);
    for (int c = 0; c < nch; c++) {
        if (c + 1 < nch) {
            load_chunk(c + 1);
            asm volatile("cp.async.wait_group 1;" ::: "memory");
        } else {
            asm volatile("cp.async.wait_group 0;" ::: "memory");
        }
        __syncthreads();
        compute_chunk(c & 1);
        __syncthreads();
    }

    // ---- epilogue: gamma * acc + bias (+ exact GELU + bf16 hi/lo split) ----
    const float gamma = g_gamma[gslot];
    #pragma unroll
    for (int mi = 0; mi < 4; mi++) {
        #pragma unroll
        for (int half = 0; half < 2; half++) {
            int gr = m0 + wm * 64 + mi * 16 + (lane >> 2) + half * 8;
            if (gr >= M) continue;
            #pragma unroll
            for (int ni = 0; ni < 4; ni++) {
                int gc = n0 + wn * 32 + ni * 8 + 2 * (lane & 3);
                float v0 = acc[mi][ni][half * 2 + 0] * gamma + bias[gc];
                float v1 = acc[mi][ni][half * 2 + 1] * gamma + bias[gc + 1];
                if (GELU_SPLIT) {
                    v0 = 0.5f * v0 * (1.0f + erff(v0 * 0.70710678118654752f));
                    v1 = 0.5f * v1 * (1.0f + erff(v1 * 0.70710678118654752f));
                    __nv_bfloat16 h0 = __float2bfloat16(v0);
                    __nv_bfloat16 l0 = __float2bfloat16(v0 - __bfloat162float(h0));
                    __nv_bfloat16 h1 = __float2bfloat16(v1);
                    __nv_bfloat16 l1 = __float2bfloat16(v1 - __bfloat162float(h1));
                    __nv_bfloat162 p0; p0.x = h0; p0.y = l0;
                    __nv_bfloat162 p1; p1.x = h1; p1.y = l1;
                    uint2 st = make_uint2(*(uint32_t*)&p0, *(uint32_t*)&p1);
                    *(uint2*)((uint32_t*)Cout + (size_t)gr * N + gc) = st;
                } else {
                    *(float2*)((float*)Cout + (size_t)gr * N + gc) =
                        make_float2(v0, v1);
                }
            }
        }
    }
}

// ---------------------------------------------------------------------------
// Launch
// ---------------------------------------------------------------------------
extern "C" void kernel_launch(void* const* d_in, const int* in_sizes, int n_in,
                              void* d_out, int out_size) {
    const float* x  = (const float*)d_in[0];
    const float* w1 = (const float*)d_in[1];
    const float* b1 = (const float*)d_in[2];
    const float* w2 = (const float*)d_in[3];
    const float* b2 = (const float*)d_in[4];
    float* out = (float*)d_out;

    __nv_bfloat162 *p_xs, *p_hs, *p_w1d, *p_w2d;
    cudaGetSymbolAddress((void**)&p_xs,  g_xs);
    cudaGetSymbolAddress((void**)&p_hs,  g_hs);
    cudaGetSymbolAddress((void**)&p_w1d, g_w1d);
    cudaGetSymbolAddress((void**)&p_w2d, g_w2d);

    const int NW = HQ * DQ;    // 2359296
    const int NX = MQ * DQ;    // 9682944
    const int SMEM_DYN = 2 * 32768;  // 64KB: 2 x (A 16K + B 16K)

    static bool attr_done = false;
    if (!attr_done) {
        cudaFuncSetAttribute(hmma_gemm<1>,
            cudaFuncAttributeMaxDynamicSharedMemorySize, SMEM_DYN);
        cudaFuncSetAttribute(hmma_gemm<0>,
            cudaFuncAttributeMaxDynamicSharedMemorySize, SMEM_DYN);
        attr_done = true;
    }

    abs_sum_kernel<<<512, 256>>>(w1, NW, 0);
    abs_sum_kernel<<<512, 256>>>(w2, NW, 1);
    finalize_gamma_kernel<<<1, 512>>>(NW, NW);

    quant_dup_kernel<<<(NW + 255) / 256, 256>>>(w1, p_w1d, NW, 0);
    quant_dup_kernel<<<(NW + 255) / 256, 256>>>(w2, p_w2d, NW, 1);
    split_kernel<<<(NX + 255) / 256, 256>>>(x, p_xs, NX);

    // GEMM1: [M, 2D] x [H, 2D]^T -> gelu -> split -> hs [M, H] bf162
    {
        dim3 grid(HQ / 128, (MQ + 127) / 128);
        hmma_gemm<1><<<grid, 256, SMEM_DYN>>>(
            (const __nv_bfloat16*)p_xs, (const __nv_bfloat16*)p_w1d, b1,
            (void*)p_hs, MQ, HQ, 2 * DQ, 0);
    }
    // GEMM2: [M, 2H] x [D, 2H]^T -> + b2 -> out fp32
    {
        dim3 grid(DQ / 128, (MQ + 127) / 128);
        hmma_gemm<0><<<grid, 256, SMEM_DYN>>>(
            (const __nv_bfloat16*)p_hs, (const __nv_bfloat16*)p_w2d, b2,
            (void*)out, MQ, DQ, 2 * HQ, 1);
    }
}